// round 5
// baseline (speedup 1.0000x reference)
#include <cuda_runtime.h>
#include <cstdint>

// Problem dims (fixed by the reference)
#define T_ 512
#define B_ 128
#define D_ 256
#define H_ 256

typedef unsigned long long ull;

// ---------------------------------------------------------------------------
// f32x2 helpers (sm_100 packed fp32 pipe: 2 FMAs per instruction)
// ---------------------------------------------------------------------------
__device__ __forceinline__ ull f32x2_pack(float x, float y) {
    ull d;
    asm("mov.b64 %0, {%1, %2};"
        : "=l"(d) : "r"(__float_as_uint(x)), "r"(__float_as_uint(y)));
    return d;
}
__device__ __forceinline__ void f32x2_unpack(ull a, float& x, float& y) {
    unsigned lo, hi;
    asm("mov.b64 {%0, %1}, %2;" : "=r"(lo), "=r"(hi) : "l"(a));
    x = __uint_as_float(lo);
    y = __uint_as_float(hi);
}
__device__ __forceinline__ void ffma2(ull& d, ull a, ull b) {
    asm("fma.rn.f32x2 %0, %1, %2, %0;" : "+l"(d) : "l"(a), "l"(b));
}

// ---------------------------------------------------------------------------
// Phase 1: Z[m][n] = sum_d X[m][d] * Wi[n][d] + bh[n]   (m = t*B + b)
// Written directly into d_out (same shape as the final output).
// ---------------------------------------------------------------------------
__global__ void __launch_bounds__(256, 2) rnn_wx_kernel(
    const float* __restrict__ X, const float* __restrict__ Wi,
    const float* __restrict__ bh, float* __restrict__ out)
{
    __shared__ __align__(16) float As[16][132];  // [k][m], padded
    __shared__ __align__(16) float Bs[16][132];  // [k][n], padded

    const int tid = threadIdx.x;
    const int tx = tid & 15;   // col group (8 cols each)
    const int ty = tid >> 4;   // row group (8 rows each)
    const int bx = blockIdx.x & 1;
    const int by = blockIdx.x >> 1;
    const int m0 = by * 128;
    const int n0 = bx * 128;

    const float* Ag = X  + (size_t)m0 * D_;
    const float* Bg = Wi + (size_t)n0 * D_;

    ull acc[8][4];
#pragma unroll
    for (int i = 0; i < 8; i++)
#pragma unroll
        for (int j = 0; j < 4; j++) acc[i][j] = 0ull;

    const int lr = tid >> 2;          // 0..63 (plus +64 pass)
    const int lk = (tid & 3) * 4;     // k offset of this thread's float4

    for (int k0 = 0; k0 < D_; k0 += 16) {
#pragma unroll
        for (int p = 0; p < 128; p += 64) {
            float4 va = *(const float4*)(Ag + (size_t)(lr + p) * D_ + k0 + lk);
            As[lk + 0][lr + p] = va.x;
            As[lk + 1][lr + p] = va.y;
            As[lk + 2][lr + p] = va.z;
            As[lk + 3][lr + p] = va.w;
            float4 vb = *(const float4*)(Bg + (size_t)(lr + p) * D_ + k0 + lk);
            Bs[lk + 0][lr + p] = vb.x;
            Bs[lk + 1][lr + p] = vb.y;
            Bs[lk + 2][lr + p] = vb.z;
            Bs[lk + 3][lr + p] = vb.w;
        }
        __syncthreads();

#pragma unroll
        for (int k = 0; k < 16; k++) {
            float4 a0 = *(const float4*)&As[k][ty * 8];
            float4 a1 = *(const float4*)&As[k][ty * 8 + 4];
            ulonglong2 q0 = *(const ulonglong2*)&Bs[k][tx * 8];
            ulonglong2 q1 = *(const ulonglong2*)&Bs[k][tx * 8 + 4];
            ull bv[4];
            bv[0] = q0.x; bv[1] = q0.y; bv[2] = q1.x; bv[3] = q1.y;
            ull ad[8];
            ad[0] = f32x2_pack(a0.x, a0.x);
            ad[1] = f32x2_pack(a0.y, a0.y);
            ad[2] = f32x2_pack(a0.z, a0.z);
            ad[3] = f32x2_pack(a0.w, a0.w);
            ad[4] = f32x2_pack(a1.x, a1.x);
            ad[5] = f32x2_pack(a1.y, a1.y);
            ad[6] = f32x2_pack(a1.z, a1.z);
            ad[7] = f32x2_pack(a1.w, a1.w);
#pragma unroll
            for (int i = 0; i < 8; i++) {
#pragma unroll
                for (int j = 0; j < 4; j++) ffma2(acc[i][j], ad[i], bv[j]);
            }
        }
        __syncthreads();
    }

    // Epilogue: add bias, store
    float4 bb0 = *(const float4*)(bh + n0 + tx * 8);
    float4 bb1 = *(const float4*)(bh + n0 + tx * 8 + 4);
#pragma unroll
    for (int i = 0; i < 8; i++) {
        float c0, c1, c2, c3, c4, c5, c6, c7;
        f32x2_unpack(acc[i][0], c0, c1);
        f32x2_unpack(acc[i][1], c2, c3);
        f32x2_unpack(acc[i][2], c4, c5);
        f32x2_unpack(acc[i][3], c6, c7);
        float4 o0 = make_float4(c0 + bb0.x, c1 + bb0.y, c2 + bb0.z, c3 + bb0.w);
        float4 o1 = make_float4(c4 + bb1.x, c5 + bb1.y, c6 + bb1.z, c7 + bb1.w);
        float* orow = out + (size_t)(m0 + ty * 8 + i) * H_ + n0 + tx * 8;
        *(float4*)(orow)     = o0;
        *(float4*)(orow + 4) = o1;
    }
}

// ---------------------------------------------------------------------------
// Phase 2: recurrent loop. 64 clusters x 2 CTAs. Each cluster owns 2 batch
// rows; CTA rank r owns output columns [r*128, r*128+128) with its half of
// Wh held in registers (k-pair packed for f32x2).
//
// Per-step sync: mbarrier handshake (NOT barrier.cluster — that costs ~490cy
// + CCTL.IVALL L1 flush per step). Protocol:
//   compute -> stores (g0/g1: local smem + STG out; g2/g3: DSMEM to peer)
//   -> __syncthreads (all local reads+stores done)
//   -> g2/g3 lanes: mbarrier.arrive.release.cluster on PEER mbar (256 arr.)
//   -> all: try_wait.parity.acquire.cluster on LOCAL mbar.
// ---------------------------------------------------------------------------
__global__ void __cluster_dims__(2, 1, 1) __launch_bounds__(512, 1)
rnn_rec_kernel(const float* __restrict__ h0, const float* __restrict__ Wh,
               float* __restrict__ out)
{
    __shared__ __align__(16) float h_sm[2][2][H_];  // [buf][row][k]
    __shared__ __align__(8) ull mbar;

    const int tid  = threadIdx.x;
    const int warp = tid >> 5;
    const int lane = tid & 31;
    const int jloc = warp * 8 + (lane >> 2);  // 0..127 local column
    const int g    = lane & 3;                // k-quarter: [g*64, g*64+64)
    unsigned rank;
    asm("mov.u32 %0, %%cluster_ctarank;" : "=r"(rank));
    const int cid = blockIdx.x >> 1;
    const int b0  = cid * 2;
    const int col = (int)rank * 128 + jloc;   // global column 0..255

    // Wh[col][g*64 .. g*64+63] into 32 k-pair registers
    ull w2[32];
    {
        const ulonglong2* wp =
            (const ulonglong2*)(Wh + (size_t)col * H_ + g * 64);
#pragma unroll
        for (int i = 0; i < 16; i++) {
            ulonglong2 v = wp[i];
            w2[2 * i]     = v.x;
            w2[2 * i + 1] = v.y;
        }
    }

    // Init h buffer 0 with h0 (512 threads -> 2 rows x 256 cols)
    {
        const int row = tid >> 8;
        const int k   = tid & 255;
        h_sm[0][row][k] = h0[(size_t)(b0 + row) * H_ + k];
    }

    // Init mbarrier: expects 256 remote arrivals per phase
    if (tid == 0) {
        unsigned ma;
        asm("{ .reg .u64 t; cvta.to.shared.u64 t, %1; cvt.u32.u64 %0, t; }"
            : "=r"(ma) : "l"(&mbar));
        asm volatile("mbarrier.init.shared.b64 [%0], 256;" ::"r"(ma) : "memory");
    }

    // Z prefetch for t=0 (all lanes hold both rows' inputs)
    float xi0 = out[(size_t)b0 * H_ + col];
    float xi1 = out[(size_t)(b0 + 1) * H_ + col];

    // Local/peer shared addresses
    unsigned h_loc, mb_loc;
    asm("{ .reg .u64 t; cvta.to.shared.u64 t, %1; cvt.u32.u64 %0, t; }"
        : "=r"(h_loc) : "l"(&h_sm[0][0][0]));
    asm("{ .reg .u64 t; cvta.to.shared.u64 t, %1; cvt.u32.u64 %0, t; }"
        : "=r"(mb_loc) : "l"(&mbar));
    unsigned h_rem, mb_rem;
    asm("mapa.shared::cluster.u32 %0, %1, %2;"
        : "=r"(h_rem) : "r"(h_loc), "r"(rank ^ 1u));
    asm("mapa.shared::cluster.u32 %0, %1, %2;"
        : "=r"(mb_rem) : "r"(mb_loc), "r"(rank ^ 1u));

    __syncthreads();
    // One-time cluster barrier: both CTAs' mbarrier init + h buffers visible
    asm volatile("barrier.cluster.arrive.aligned;" ::: "memory");
    asm volatile("barrier.cluster.wait.aligned;" ::: "memory");

#pragma unroll 1
    for (int t = 0; t < T_; t++) {
        const int buf = t & 1;
        ull acc0 = 0ull, acc1 = 0ull;
        const ulonglong2* hp0 = (const ulonglong2*)&h_sm[buf][0][g * 64];
        const ulonglong2* hp1 = (const ulonglong2*)&h_sm[buf][1][g * 64];
#pragma unroll
        for (int i = 0; i < 16; i++) {
            ulonglong2 ha = hp0[i];
            ffma2(acc0, ha.x, w2[2 * i]);
            ffma2(acc0, ha.y, w2[2 * i + 1]);
            ulonglong2 hb = hp1[i];
            ffma2(acc1, hb.x, w2[2 * i]);
            ffma2(acc1, hb.y, w2[2 * i + 1]);
        }
        float e0, o0e, e1, o1e;
        f32x2_unpack(acc0, e0, o0e);
        f32x2_unpack(acc1, e1, o1e);
        float r0 = e0 + o0e;
        float r1 = e1 + o1e;
        // xor-reduce across the 4 k-quarters: ALL lanes end with full sums
        r0 += __shfl_xor_sync(0xffffffffu, r0, 1);
        r0 += __shfl_xor_sync(0xffffffffu, r0, 2);
        r1 += __shfl_xor_sync(0xffffffffu, r1, 1);
        r1 += __shfl_xor_sync(0xffffffffu, r1, 2);

        // every lane computes both sigmoids (symmetric epilogue)
        const float hn0 = 1.0f / (1.0f + __expf(-(xi0 + r0)));
        const float hn1 = 1.0f / (1.0f + __expf(-(xi1 + r1)));
        const int nb = buf ^ 1;

        if (g == 0) {
            h_sm[nb][0][col] = hn0;                       // local row0
            out[((size_t)t * B_ + b0) * H_ + col] = hn0;  // emit row0
        } else if (g == 1) {
            h_sm[nb][1][col] = hn1;                       // local row1
            out[((size_t)t * B_ + b0 + 1) * H_ + col] = hn1;  // emit row1
        } else if (g == 2) {
            const unsigned off = h_rem + (unsigned)(((nb * 2) * H_ + col) * 4);
            asm volatile("st.shared::cluster.f32 [%0], %1;"
                         ::"r"(off), "f"(hn0) : "memory");
        } else {
            const unsigned off =
                h_rem + (unsigned)(((nb * 2 + 1) * H_ + col) * 4);
            asm volatile("st.shared::cluster.f32 [%0], %1;"
                         ::"r"(off), "f"(hn1) : "memory");
        }

        // prefetch Z for t+1 (all lanes; L1-resident, off critical path)
        if (t + 1 < T_) {
            const float* ip = out + ((size_t)(t + 1) * B_ + b0) * H_ + col;
            xi0 = ip[0];
            xi1 = ip[H_];
        }

        // local ordering: all reads of buf + local stores complete
        __syncthreads();

        // remote-storing lanes release their stores into peer's mbar
        if (g >= 2) {
            asm volatile(
                "mbarrier.arrive.release.cluster.shared::cluster.b64 _, [%0];"
                ::"r"(mb_rem) : "memory");
        }

        // wait for peer's 256 arrivals of this phase
        {
            const unsigned parity = (unsigned)(t & 1);
            unsigned done;
            asm volatile(
                "{\n\t"
                ".reg .pred p;\n\t"
                "mbarrier.try_wait.parity.acquire.cluster.shared::cta.b64 p, [%1], %2;\n\t"
                "selp.b32 %0, 1, 0, p;\n\t"
                "}"
                : "=r"(done) : "r"(mb_loc), "r"(parity) : "memory");
            if (!done) {
                asm volatile(
                    "{\n\t"
                    ".reg .pred P1;\n\t"
                    "WL_%=:\n\t"
                    "mbarrier.try_wait.parity.acquire.cluster.shared::cta.b64 P1, [%0], %1, 0x989680;\n\t"
                    "@P1 bra.uni WD_%=;\n\t"
                    "bra.uni WL_%=;\n\t"
                    "WD_%=:\n\t"
                    "}"
                    ::"r"(mb_loc), "r"(parity) : "memory");
            }
        }
    }
}

// ---------------------------------------------------------------------------
// Launch
// ---------------------------------------------------------------------------
extern "C" void kernel_launch(void* const* d_in, const int* in_sizes, int n_in,
                              void* d_out, int out_size) {
    const float* X  = (const float*)d_in[0];
    const float* h0 = (const float*)d_in[1];
    const float* Wi = (const float*)d_in[2];
    const float* Wh = (const float*)d_in[3];
    const float* bh = (const float*)d_in[4];
    float* out = (float*)d_out;

    // Phase 1: Z = X @ Wi^T + bh  ->  d_out
    rnn_wx_kernel<<<1024, 256>>>(X, Wi, bh, out);

    // Phase 2: recurrence, in place over d_out
    rnn_rec_kernel<<<128, 512>>>(h0, Wh, out);
}

// round 6
// speedup vs baseline: 3.0807x; 3.0807x over previous
#include <cuda_runtime.h>
#include <cstdint>

// Problem dims (fixed by the reference)
#define T_ 512
#define B_ 128
#define D_ 256
#define H_ 256

typedef unsigned long long ull;

// ---------------------------------------------------------------------------
// f32x2 helpers (sm_100 packed fp32 pipe: 2 FMAs per instruction)
// ---------------------------------------------------------------------------
__device__ __forceinline__ ull f32x2_pack(float x, float y) {
    ull d;
    asm("mov.b64 %0, {%1, %2};"
        : "=l"(d) : "r"(__float_as_uint(x)), "r"(__float_as_uint(y)));
    return d;
}
__device__ __forceinline__ void f32x2_unpack(ull a, float& x, float& y) {
    unsigned lo, hi;
    asm("mov.b64 {%0, %1}, %2;" : "=r"(lo), "=r"(hi) : "l"(a));
    x = __uint_as_float(lo);
    y = __uint_as_float(hi);
}
__device__ __forceinline__ void ffma2(ull& d, ull a, ull b) {
    asm("fma.rn.f32x2 %0, %1, %2, %0;" : "+l"(d) : "l"(a), "l"(b));
}
__device__ __forceinline__ void fmul2(ull& d, ull a, ull b) {
    asm("mul.rn.f32x2 %0, %1, %2;" : "=l"(d) : "l"(a), "l"(b));
}

// ---------------------------------------------------------------------------
// Phase 1: Z[m][n] = sum_d X[m][d] * Wi[n][d] + bh[n]   (m = t*B + b)
// Written directly into d_out (same shape as the final output). Unchanged.
// ---------------------------------------------------------------------------
__global__ void __launch_bounds__(256, 2) rnn_wx_kernel(
    const float* __restrict__ X, const float* __restrict__ Wi,
    const float* __restrict__ bh, float* __restrict__ out)
{
    __shared__ __align__(16) float As[16][132];  // [k][m], padded
    __shared__ __align__(16) float Bs[16][132];  // [k][n], padded

    const int tid = threadIdx.x;
    const int tx = tid & 15;   // col group (8 cols each)
    const int ty = tid >> 4;   // row group (8 rows each)
    const int bx = blockIdx.x & 1;
    const int by = blockIdx.x >> 1;
    const int m0 = by * 128;
    const int n0 = bx * 128;

    const float* Ag = X  + (size_t)m0 * D_;
    const float* Bg = Wi + (size_t)n0 * D_;

    ull acc[8][4];
#pragma unroll
    for (int i = 0; i < 8; i++)
#pragma unroll
        for (int j = 0; j < 4; j++) acc[i][j] = 0ull;

    const int lr = tid >> 2;          // 0..63 (plus +64 pass)
    const int lk = (tid & 3) * 4;     // k offset of this thread's float4

    for (int k0 = 0; k0 < D_; k0 += 16) {
#pragma unroll
        for (int p = 0; p < 128; p += 64) {
            float4 va = *(const float4*)(Ag + (size_t)(lr + p) * D_ + k0 + lk);
            As[lk + 0][lr + p] = va.x;
            As[lk + 1][lr + p] = va.y;
            As[lk + 2][lr + p] = va.z;
            As[lk + 3][lr + p] = va.w;
            float4 vb = *(const float4*)(Bg + (size_t)(lr + p) * D_ + k0 + lk);
            Bs[lk + 0][lr + p] = vb.x;
            Bs[lk + 1][lr + p] = vb.y;
            Bs[lk + 2][lr + p] = vb.z;
            Bs[lk + 3][lr + p] = vb.w;
        }
        __syncthreads();

#pragma unroll
        for (int k = 0; k < 16; k++) {
            float4 a0 = *(const float4*)&As[k][ty * 8];
            float4 a1 = *(const float4*)&As[k][ty * 8 + 4];
            ulonglong2 q0 = *(const ulonglong2*)&Bs[k][tx * 8];
            ulonglong2 q1 = *(const ulonglong2*)&Bs[k][tx * 8 + 4];
            ull bv[4];
            bv[0] = q0.x; bv[1] = q0.y; bv[2] = q1.x; bv[3] = q1.y;
            ull ad[8];
            ad[0] = f32x2_pack(a0.x, a0.x);
            ad[1] = f32x2_pack(a0.y, a0.y);
            ad[2] = f32x2_pack(a0.z, a0.z);
            ad[3] = f32x2_pack(a0.w, a0.w);
            ad[4] = f32x2_pack(a1.x, a1.x);
            ad[5] = f32x2_pack(a1.y, a1.y);
            ad[6] = f32x2_pack(a1.z, a1.z);
            ad[7] = f32x2_pack(a1.w, a1.w);
#pragma unroll
            for (int i = 0; i < 8; i++) {
#pragma unroll
                for (int j = 0; j < 4; j++) ffma2(acc[i][j], ad[i], bv[j]);
            }
        }
        __syncthreads();
    }

    // Epilogue: add bias, store
    float4 bb0 = *(const float4*)(bh + n0 + tx * 8);
    float4 bb1 = *(const float4*)(bh + n0 + tx * 8 + 4);
#pragma unroll
    for (int i = 0; i < 8; i++) {
        float c0, c1, c2, c3, c4, c5, c6, c7;
        f32x2_unpack(acc[i][0], c0, c1);
        f32x2_unpack(acc[i][1], c2, c3);
        f32x2_unpack(acc[i][2], c4, c5);
        f32x2_unpack(acc[i][3], c6, c7);
        float4 o0 = make_float4(c0 + bb0.x, c1 + bb0.y, c2 + bb0.z, c3 + bb0.w);
        float4 o1 = make_float4(c4 + bb1.x, c5 + bb1.y, c6 + bb1.z, c7 + bb1.w);
        float* orow = out + (size_t)(m0 + ty * 8 + i) * H_ + n0 + tx * 8;
        *(float4*)(orow)     = o0;
        *(float4*)(orow + 4) = o1;
    }
}

// ---------------------------------------------------------------------------
// Phase 2: recurrence. 64 clusters x 2 CTAs, 512 thr/CTA. CTA rank r owns
// cols [r*128, r*128+128).
//
// NEW micro-tile (kills the LDS broadcast/bank-conflict wall from R2/R5):
//   warp w owns cols colbase = r*128 + w*8 .. +8
//   lane l owns k-set {4l..4l+3} U {128+4l..128+4l+3}  (8 k, 4 f32x2 pairs)
//   Wh regs: 8 cols x 4 pairs = 32 ull.
//   h load per row = 2x LDS.128 at lane*16B (conflict-free, 0% redundancy):
//   4 LDS.128/warp/step (was 32 with 8x broadcast + conflicts).
// Reduction: 5-round value-halving butterfly (16 SHFL + 16 FADD/thread).
// Final: lane pair (2m,2m+1) holds output (row=b4, col=colbase+b3b2b1).
//   even lane: local smem h + STG out; odd lane: DSMEM store + arrive.
// ---------------------------------------------------------------------------
__global__ void __cluster_dims__(2, 1, 1) __launch_bounds__(512, 1)
rnn_rec_kernel(const float* __restrict__ h0, const float* __restrict__ Wh,
               float* __restrict__ out)
{
    __shared__ __align__(16) float h_sm[2][2][H_];  // [buf][row][k]
    __shared__ __align__(8) ull mbar;

    const int tid  = threadIdx.x;
    const int warp = tid >> 5;
    const int lane = tid & 31;
    unsigned rank;
    asm("mov.u32 %0, %%cluster_ctarank;" : "=r"(rank));
    const int cid = blockIdx.x >> 1;
    const int b0  = cid * 2;
    const int colbase = (int)rank * 128 + warp * 8;
    const int l4 = lane * 4;

    // Wh: 8 cols x 8 k-values -> 32 f32x2 regs
    ull w[8][4];
#pragma unroll
    for (int cc = 0; cc < 8; cc++) {
        const float* wr = Wh + (size_t)(colbase + cc) * H_;
        ulonglong2 qa = *(const ulonglong2*)(wr + l4);
        ulonglong2 qb = *(const ulonglong2*)(wr + 128 + l4);
        w[cc][0] = qa.x; w[cc][1] = qa.y;
        w[cc][2] = qb.x; w[cc][3] = qb.y;
    }

    // Init h buffer 0 with h0 (512 threads -> 2 rows x 256 cols)
    {
        const int row = tid >> 8;
        const int k   = tid & 255;
        h_sm[0][row][k] = h0[(size_t)(b0 + row) * H_ + k];
    }

    // mbarrier: 256 arrivals (odd lanes of peer) per phase
    if (tid == 0) {
        unsigned ma;
        asm("{ .reg .u64 t; cvta.to.shared.u64 t, %1; cvt.u32.u64 %0, t; }"
            : "=r"(ma) : "l"(&mbar));
        asm volatile("mbarrier.init.shared.b64 [%0], 256;" ::"r"(ma) : "memory");
    }

    // Output mapping for this lane (valid after the butterfly):
    const int orow = (lane >> 4) & 1;                 // bit4
    const int ocol = colbase + ((lane >> 1) & 7);     // bits 3..1
    const int opar = lane & 1;                        // duplicate flag

    // Z prefetch for t=0
    float xi = out[(size_t)(b0 + orow) * H_ + ocol];

    // Local/peer shared addresses
    unsigned h_loc, mb_loc;
    asm("{ .reg .u64 t; cvta.to.shared.u64 t, %1; cvt.u32.u64 %0, t; }"
        : "=r"(h_loc) : "l"(&h_sm[0][0][0]));
    asm("{ .reg .u64 t; cvta.to.shared.u64 t, %1; cvt.u32.u64 %0, t; }"
        : "=r"(mb_loc) : "l"(&mbar));
    unsigned h_rem, mb_rem;
    asm("mapa.shared::cluster.u32 %0, %1, %2;"
        : "=r"(h_rem) : "r"(h_loc), "r"(rank ^ 1u));
    asm("mapa.shared::cluster.u32 %0, %1, %2;"
        : "=r"(mb_rem) : "r"(mb_loc), "r"(rank ^ 1u));

    __syncthreads();
    // One-time cluster barrier: both CTAs' mbar init + h buffers visible
    asm volatile("barrier.cluster.arrive.aligned;" ::: "memory");
    asm volatile("barrier.cluster.wait.aligned;" ::: "memory");

#pragma unroll 1
    for (int t = 0; t < T_; t++) {
        const int buf = t & 1;
        // conflict-free distinct loads: lane l -> h[4l..4l+4), h[128+4l..)
        ulonglong2 q0a = *(const ulonglong2*)&h_sm[buf][0][l4];
        ulonglong2 q0b = *(const ulonglong2*)&h_sm[buf][0][128 + l4];
        ulonglong2 q1a = *(const ulonglong2*)&h_sm[buf][1][l4];
        ulonglong2 q1b = *(const ulonglong2*)&h_sm[buf][1][128 + l4];

        float a[8], b[8];
        {
            ull acc[8];
#pragma unroll
            for (int cc = 0; cc < 8; cc++) {
                fmul2(acc[cc], q0a.x, w[cc][0]);
                ffma2(acc[cc], q0a.y, w[cc][1]);
                ffma2(acc[cc], q0b.x, w[cc][2]);
                ffma2(acc[cc], q0b.y, w[cc][3]);
                float x, y;
                f32x2_unpack(acc[cc], x, y);
                a[cc] = x + y;
            }
#pragma unroll
            for (int cc = 0; cc < 8; cc++) {
                fmul2(acc[cc], q1a.x, w[cc][0]);
                ffma2(acc[cc], q1a.y, w[cc][1]);
                ffma2(acc[cc], q1b.x, w[cc][2]);
                ffma2(acc[cc], q1b.y, w[cc][3]);
                float x, y;
                f32x2_unpack(acc[cc], x, y);
                b[cc] = x + y;
            }
        }

        // 5-round value-halving butterfly over 32 lanes
        // R1 (xor16): keep row = bit4
        float s1[8];
        {
            const bool hi = (lane & 16) != 0;
#pragma unroll
            for (int j = 0; j < 8; j++) {
                float keep = hi ? b[j] : a[j];
                float give = hi ? a[j] : b[j];
                s1[j] = keep + __shfl_xor_sync(0xffffffffu, give, 16);
            }
        }
        // R2 (xor8): keep col-half = bit3
        float s2[4];
        {
            const bool hi = (lane & 8) != 0;
#pragma unroll
            for (int j = 0; j < 4; j++) {
                float keep = hi ? s1[j + 4] : s1[j];
                float give = hi ? s1[j] : s1[j + 4];
                s2[j] = keep + __shfl_xor_sync(0xffffffffu, give, 8);
            }
        }
        // R3 (xor4): keep pair = bit2
        float s3[2];
        {
            const bool hi = (lane & 4) != 0;
#pragma unroll
            for (int j = 0; j < 2; j++) {
                float keep = hi ? s2[j + 2] : s2[j];
                float give = hi ? s2[j] : s2[j + 2];
                s3[j] = keep + __shfl_xor_sync(0xffffffffu, give, 4);
            }
        }
        // R4 (xor2): keep one = bit1
        float s4;
        {
            const bool hi = (lane & 2) != 0;
            float keep = hi ? s3[1] : s3[0];
            float give = hi ? s3[0] : s3[1];
            s4 = keep + __shfl_xor_sync(0xffffffffu, give, 2);
        }
        // R5 (xor1): full add, both lanes keep
        s4 += __shfl_xor_sync(0xffffffffu, s4, 1);

        // sigmoid (one per lane)
        const float hn = 1.0f / (1.0f + __expf(-(xi + s4)));
        const int nb = buf ^ 1;

        if (!opar) {
            h_sm[nb][orow][ocol] = hn;                             // local
            out[((size_t)t * B_ + b0 + orow) * H_ + ocol] = hn;    // emit
        } else {
            const unsigned off =
                h_rem + (unsigned)(((nb * 2 + orow) * H_ + ocol) * 4);
            asm volatile("st.shared::cluster.f32 [%0], %1;"
                         ::"r"(off), "f"(hn) : "memory");
        }

        // prefetch Z for t+1
        if (t + 1 < T_) {
            xi = out[((size_t)(t + 1) * B_ + b0 + orow) * H_ + ocol];
        }

        // local ordering: all reads of buf + local stores complete
        __syncthreads();

        // remote-storing lanes release their stores into peer's mbar
        if (opar) {
            asm volatile(
                "mbarrier.arrive.release.cluster.shared::cluster.b64 _, [%0];"
                ::"r"(mb_rem) : "memory");
        }

        // wait for peer's 256 arrivals of this phase
        {
            const unsigned parity = (unsigned)(t & 1);
            unsigned done;
            asm volatile(
                "{\n\t"
                ".reg .pred p;\n\t"
                "mbarrier.try_wait.parity.acquire.cluster.shared::cta.b64 p, [%1], %2;\n\t"
                "selp.b32 %0, 1, 0, p;\n\t"
                "}"
                : "=r"(done) : "r"(mb_loc), "r"(parity) : "memory");
            if (!done) {
                asm volatile(
                    "{\n\t"
                    ".reg .pred P1;\n\t"
                    "WL_%=:\n\t"
                    "mbarrier.try_wait.parity.acquire.cluster.shared::cta.b64 P1, [%0], %1, 0x989680;\n\t"
                    "@P1 bra.uni WD_%=;\n\t"
                    "bra.uni WL_%=;\n\t"
                    "WD_%=:\n\t"
                    "}"
                    ::"r"(mb_loc), "r"(parity) : "memory");
            }
        }
    }
}

// ---------------------------------------------------------------------------
// Launch
// ---------------------------------------------------------------------------
extern "C" void kernel_launch(void* const* d_in, const int* in_sizes, int n_in,
                              void* d_out, int out_size) {
    const float* X  = (const float*)d_in[0];
    const float* h0 = (const float*)d_in[1];
    const float* Wi = (const float*)d_in[2];
    const float* Wh = (const float*)d_in[3];
    const float* bh = (const float*)d_in[4];
    float* out = (float*)d_out;

    // Phase 1: Z = X @ Wi^T + bh  ->  d_out
    rnn_wx_kernel<<<1024, 256>>>(X, Wi, bh, out);

    // Phase 2: recurrence, in place over d_out
    rnn_rec_kernel<<<128, 512>>>(h0, Wh, out);
}